// round 7
// baseline (speedup 1.0000x reference)
#include <cuda_runtime.h>

// GRU persistent kernel v2.
// - 128 CTAs x 256 threads, warp tile 16 rows x 4 cols (thread: 2 rows x 1 col)
//   -> per-warp weight SMEM traffic cut 4x vs v1, inputs conflict-free.
// - h/rh/x SMEM rows padded to stride == 4 (mod 32) floats: conflict-free
//   LDS.128 subphases for the 8-lane row reads.
// - Barriers are per-batch-tile GROUPS of 16 CTAs (batch tiles independent).
// - Overlap: barrier A hides candidate x-part; barrier B hides x(t+1) prefetch
//   plus the z/r x-part for t+1 (h-independent).

#define SEQLEN 512
#define BATCHN 256
#define INPUTN 128
#define HID    256
#define NBLK   128
#define NBT    8       // batch-tile groups
#define BT     32      // rows per batch tile
#define HS     16      // hidden cols per slice
#define NGRP   16      // CTAs per barrier group
#define WPAD   388     // weight row pad (floats), 97 x 16B
#define WP4    97
#define GS4    (HS*WP4)    // 1552 16B-chunks per gate
#define HPAD   260        // h/rh row pad: 260 % 32 == 4 -> conflict-free
#define H16    65         // 260/4 16B chunks
#define XPAD   132        // x row pad
#define X16    33

__device__ float    g_h [BATCHN * HID];
__device__ float    g_rh[BATCHN * HID];
__device__ unsigned g_count[NBT * 32];   // padded: one flag per 128B
__device__ unsigned g_sense[NBT * 32];

__device__ __forceinline__ void ffma2(unsigned long long &acc,
                                      unsigned long long a,
                                      unsigned long long b) {
    asm("fma.rn.f32x2 %0, %1, %2, %0;" : "+l"(acc) : "l"(a), "l"(b));
}
__device__ __forceinline__ float f2sum(unsigned long long v) {
    return __uint_as_float((unsigned)v) + __uint_as_float((unsigned)(v >> 32));
}
__device__ __forceinline__ float sigmoidf_(float a) {
    return 1.0f / (1.0f + __expf(-a));
}
__device__ __forceinline__ float tanhf_(float a) {
    return 2.0f / (1.0f + __expf(-2.0f * a)) - 1.0f;
}

// group barrier: arrive (non-blocking) ... overlap work ... wait
__device__ __forceinline__ void grp_arrive(unsigned &sense, unsigned *cnt, unsigned *sns) {
    __syncthreads();
    if (threadIdx.x == 0) {
        sense ^= 1u;
        __threadfence();
        unsigned prev = atomicAdd(cnt, 1u);
        if (prev == NGRP - 1u) {
            atomicExch(cnt, 0u);
            __threadfence();
            atomicExch(sns, sense);
        }
    }
}
__device__ __forceinline__ void grp_wait(unsigned sense, unsigned *sns) {
    if (threadIdx.x == 0) {
        while (*((volatile unsigned *)sns) != sense) { }
        __threadfence();
    }
    __syncthreads();
}

__global__ void __launch_bounds__(256, 1)
gru_persistent(const float* __restrict__ X,
               const float* __restrict__ Wz, const float* __restrict__ bz,
               const float* __restrict__ Wr, const float* __restrict__ br,
               const float* __restrict__ Wc, const float* __restrict__ bc,
               float* __restrict__ out)
{
    extern __shared__ float sm[];
    float* sW   = sm;                          // 3*16*388 = 18624 floats
    float* sB   = sm + 3 * HS * WPAD;          // 48 floats
    float* h_s  = sB + 48;                     // 32 x 260
    float* rh_s = h_s + BT * HPAD;             // 32 x 260
    float* x_s  = rh_s + BT * HPAD;            // 32 x 132

    const int tid   = threadIdx.x;
    const int bt    = blockIdx.x & (NBT - 1);
    const int hsb   = blockIdx.x >> 3;
    const int bbase = bt * BT;
    const int jbase = hsb * HS;

    unsigned *cnt = &g_count[bt * 32];
    unsigned *sns = &g_sense[bt * 32];

    unsigned sense = 0;
    if (tid == 0) sense = *((volatile unsigned *)sns);

    // ---- weights into SMEM (row-major per col, padded) ----
    {
        float4* sW4 = (float4*)sW;
        #pragma unroll
        for (int g = 0; g < 3; g++) {
            const float* W = (g == 0) ? Wz : (g == 1) ? Wr : Wc;
            const float4* W4 = (const float4*)W;
            for (int idx = tid; idx < HS * 96; idx += 256) {
                int j = idx / 96, k4 = idx % 96;
                sW4[g * GS4 + j * WP4 + k4] = W4[(jbase + j) * 96 + k4];
            }
        }
        if (tid < HS) {
            sB[tid]          = bz[jbase + tid];
            sB[HS + tid]     = br[jbase + tid];
            sB[2 * HS + tid] = bc[jbase + tid];
        }
        for (int i = tid; i < BT * HPAD; i += 256) h_s[i] = 0.0f;   // h0 = 0
    }
    // x tile for t=0
    for (int idx = tid; idx < BT * 32; idx += 256) {
        int row = idx >> 5, c4 = idx & 31;
        *(float4*)(x_s + row * XPAD + c4 * 4) =
            ((const float4*)X)[(size_t)(bbase + row) * (SEQLEN * INPUTN / 4) + c4];
    }
    __syncthreads();

    // lane map: warp tile 16 rows x 4 cols, thread 2 rows x 1 col
    const int w    = tid >> 5;
    const int l    = tid & 31;
    const int txi  = l >> 3;                 // 0..3  (col within warp)
    const int ty   = l & 7;                  // 0..7  (row within subphase)
    const int cg   = w & 3;                  // warp col group
    const int rg   = w >> 2;                 // warp row group (0,1)
    const int jloc = cg * 4 + txi;           // 0..15
    const int jg   = jbase + jloc;           // global hidden col
    const int row0 = rg * 16 + ty;
    const int row1 = row0 + 8;

    const ulonglong2* wz2 = (const ulonglong2*)sW + jloc * WP4;
    const ulonglong2* wr2 = wz2 + GS4;
    const ulonglong2* wc2 = wz2 + 2 * GS4;
    const ulonglong2* h0p  = (const ulonglong2*)h_s  + row0 * H16;
    const ulonglong2* h1p  = (const ulonglong2*)h_s  + row1 * H16;
    const ulonglong2* rh0p = (const ulonglong2*)rh_s + row0 * H16;
    const ulonglong2* rh1p = (const ulonglong2*)rh_s + row1 * H16;
    const ulonglong2* x0p  = (const ulonglong2*)x_s  + row0 * X16;
    const ulonglong2* x1p  = (const ulonglong2*)x_s  + row1 * X16;

    const float bzr = sB[jloc];
    const float brr = sB[HS + jloc];
    const float bcr = sB[2 * HS + jloc];

    // z/r x-part for t=0 (h-independent)
    unsigned long long az0 = 0, az1 = 0, ar0 = 0, ar1 = 0;
    #pragma unroll 8
    for (int k = 0; k < 32; k++) {
        ulonglong2 xv0 = x0p[k], xv1 = x1p[k];
        ulonglong2 wzv = wz2[64 + k], wrv = wr2[64 + k];
        ffma2(az0, wzv.x, xv0.x); ffma2(az0, wzv.y, xv0.y);
        ffma2(ar0, wrv.x, xv0.x); ffma2(ar0, wrv.y, xv0.y);
        ffma2(az1, wzv.x, xv1.x); ffma2(az1, wzv.y, xv1.y);
        ffma2(ar1, wrv.x, xv1.x); ffma2(ar1, wrv.y, xv1.y);
    }

    for (int t = 0; t < SEQLEN; t++) {
        // ---------- phase 1: z, r (h-part; x-part already accumulated) ----------
        #pragma unroll 8
        for (int k = 0; k < 64; k++) {
            ulonglong2 hv0 = h0p[k], hv1 = h1p[k];
            ulonglong2 wzv = wz2[k], wrv = wr2[k];
            ffma2(az0, wzv.x, hv0.x); ffma2(az0, wzv.y, hv0.y);
            ffma2(ar0, wrv.x, hv0.x); ffma2(ar0, wrv.y, hv0.y);
            ffma2(az1, wzv.x, hv1.x); ffma2(az1, wzv.y, hv1.y);
            ffma2(ar1, wrv.x, hv1.x); ffma2(ar1, wrv.y, hv1.y);
        }
        float z0 = sigmoidf_(f2sum(az0) + bzr);
        float z1 = sigmoidf_(f2sum(az1) + bzr);
        float r0 = sigmoidf_(f2sum(ar0) + brr);
        float r1 = sigmoidf_(f2sum(ar1) + brr);
        float h0old = h_s[row0 * HPAD + jg];
        float h1old = h_s[row1 * HPAD + jg];
        g_rh[(bbase + row0) * HID + jg] = r0 * h0old;
        g_rh[(bbase + row1) * HID + jg] = r1 * h1old;

        grp_arrive(sense, cnt, sns);                 // barrier A arrive

        // overlap A: candidate x-part (independent of rh)
        unsigned long long ac0 = 0, ac1 = 0;
        #pragma unroll 8
        for (int k = 0; k < 32; k++) {
            ulonglong2 xv0 = x0p[k], xv1 = x1p[k];
            ulonglong2 wcv = wc2[64 + k];
            ffma2(ac0, wcv.x, xv0.x); ffma2(ac0, wcv.y, xv0.y);
            ffma2(ac1, wcv.x, xv1.x); ffma2(ac1, wcv.y, xv1.y);
        }

        grp_wait(sense, sns);                        // barrier A wait

        // gather full r*h rows for our batch tile
        for (int idx = tid; idx < BT * 64; idx += 256) {
            int row = idx >> 6, c4 = idx & 63;
            *(float4*)(rh_s + row * HPAD + c4 * 4) =
                ((const float4*)g_rh)[(bbase + row) * 64 + c4];
        }
        __syncthreads();

        // ---------- phase 2: candidate h-part + update ----------
        #pragma unroll 8
        for (int k = 0; k < 64; k++) {
            ulonglong2 rv0 = rh0p[k], rv1 = rh1p[k];
            ulonglong2 wcv = wc2[k];
            ffma2(ac0, wcv.x, rv0.x); ffma2(ac0, wcv.y, rv0.y);
            ffma2(ac1, wcv.x, rv1.x); ffma2(ac1, wcv.y, rv1.y);
        }
        float c0 = tanhf_(f2sum(ac0) + bcr);
        float c1 = tanhf_(f2sum(ac1) + bcr);
        float hn0 = h0old + z0 * (c0 - h0old);       // (1-z)h + z*c
        float hn1 = h1old + z1 * (c1 - h1old);
        g_h[(bbase + row0) * HID + jg] = hn0;
        g_h[(bbase + row1) * HID + jg] = hn1;
        float* orow = out + (size_t)t * (BATCHN * HID);
        orow[(bbase + row0) * HID + jg] = hn0;
        orow[(bbase + row1) * HID + jg] = hn1;

        grp_arrive(sense, cnt, sns);                 // barrier B arrive

        // overlap B: x(t+1) prefetch + z/r x-part for t+1
        az0 = 0; az1 = 0; ar0 = 0; ar1 = 0;
        if (t + 1 < SEQLEN) {
            for (int idx = tid; idx < BT * 32; idx += 256) {
                int row = idx >> 5, c4 = idx & 31;
                *(float4*)(x_s + row * XPAD + c4 * 4) =
                    ((const float4*)X)[(size_t)(bbase + row) * (SEQLEN * INPUTN / 4)
                                       + (size_t)(t + 1) * 32 + c4];
            }
            __syncthreads();
            #pragma unroll 8
            for (int k = 0; k < 32; k++) {
                ulonglong2 xv0 = x0p[k], xv1 = x1p[k];
                ulonglong2 wzv = wz2[64 + k], wrv = wr2[64 + k];
                ffma2(az0, wzv.x, xv0.x); ffma2(az0, wzv.y, xv0.y);
                ffma2(ar0, wrv.x, xv0.x); ffma2(ar0, wrv.y, xv0.y);
                ffma2(az1, wzv.x, xv1.x); ffma2(az1, wzv.y, xv1.y);
                ffma2(ar1, wrv.x, xv1.x); ffma2(ar1, wrv.y, xv1.y);
            }
        }

        grp_wait(sense, sns);                        // barrier B wait

        // refresh h tile for next step
        if (t + 1 < SEQLEN) {
            for (int idx = tid; idx < BT * 64; idx += 256) {
                int row = idx >> 6, c4 = idx & 63;
                *(float4*)(h_s + row * HPAD + c4 * 4) =
                    ((const float4*)g_h)[(bbase + row) * 64 + c4];
            }
            __syncthreads();
        }
    }
}

extern "C" void kernel_launch(void* const* d_in, const int* in_sizes, int n_in,
                              void* d_out, int out_size) {
    const float* X  = (const float*)d_in[0];
    const float* Wz = (const float*)d_in[1];
    const float* bz = (const float*)d_in[2];
    const float* Wr = (const float*)d_in[3];
    const float* br = (const float*)d_in[4];
    const float* Wc = (const float*)d_in[5];
    const float* bc = (const float*)d_in[6];
    float* out = (float*)d_out;

    int smem_floats = 3 * HS * WPAD + 48 + 2 * BT * HPAD + BT * XPAD;
    int smem_bytes  = smem_floats * (int)sizeof(float);

    cudaFuncSetAttribute(gru_persistent,
                         cudaFuncAttributeMaxDynamicSharedMemorySize, smem_bytes);
    gru_persistent<<<NBLK, 256, smem_bytes>>>(X, Wz, bz, Wr, br, Wc, bc, out);
}

// round 9
// speedup vs baseline: 1.5098x; 1.5098x over previous
#include <cuda_runtime.h>

// GRU persistent v4: dual half-pipelines + 4-way cross-warp k-split tiles.
#define SEQLEN 512
#define HPADF  260     // h/rh row stride (65 granules, %8==1 -> conflict-free)
#define XPADF  132     // x row stride (33 granules)
#define WT4    1536    // float4 per gate (96 chunks x 16 cols)

__device__ float    g_h [256 * 256];
__device__ float    g_rh[256 * 256];
__device__ unsigned g_count[16 * 32];
__device__ unsigned g_sense[16 * 32];

__device__ __forceinline__ void ffma2(unsigned long long &a,
                                      unsigned long long x, unsigned long long y) {
    asm("fma.rn.f32x2 %0, %1, %2, %0;" : "+l"(a) : "l"(x), "l"(y));
}
__device__ __forceinline__ float f2sum(unsigned long long v) {
    return __uint_as_float((unsigned)v) + __uint_as_float((unsigned)(v >> 32));
}
__device__ __forceinline__ float sig_(float a) { return 1.0f / (1.0f + __expf(-a)); }
__device__ __forceinline__ float tanh_(float a) { return 2.0f / (1.0f + __expf(-2.0f * a)) - 1.0f; }
__device__ __forceinline__ void barn(int id) {
    asm volatile("bar.sync %0, 128;" :: "r"(id) : "memory");
}
__device__ __forceinline__ void grp_arrive(unsigned &sense, unsigned *cnt,
                                           unsigned *sns, int nb, int lt) {
    barn(nb);
    if (lt == 0) {
        sense ^= 1u;
        __threadfence();
        if (atomicAdd(cnt, 1u) == 15u) {
            atomicExch(cnt, 0u);
            __threadfence();
            atomicExch(sns, sense);
        }
    }
}
__device__ __forceinline__ void grp_wait(unsigned sense, unsigned *sns, int nb, int lt) {
    if (lt == 0) {
        while (*((volatile unsigned *)sns) != sense) { }
        __threadfence();
    }
    barn(nb);
}

#define ACC2(a, wv, hv) { ffma2(a, (wv).x, (hv).x); ffma2(a, (wv).y, (hv).y); }
#define ZR16(v0,v1,v2,v3,z0,z1,r0,r1) \
    ACC2(az[0],z0,v0); ACC2(az[1],z1,v0); ACC2(az[2],z0,v1); ACC2(az[3],z1,v1); \
    ACC2(az[4],z0,v2); ACC2(az[5],z1,v2); ACC2(az[6],z0,v3); ACC2(az[7],z1,v3); \
    ACC2(ar[0],r0,v0); ACC2(ar[1],r1,v0); ACC2(ar[2],r0,v1); ACC2(ar[3],r1,v1); \
    ACC2(ar[4],r0,v2); ACC2(ar[5],r1,v2); ACC2(ar[6],r0,v3); ACC2(ar[7],r1,v3);
#define C8(v0,v1,v2,v3,c0,c1) \
    ACC2(ac[0],c0,v0); ACC2(ac[1],c1,v0); ACC2(ac[2],c0,v1); ACC2(ac[3],c1,v1); \
    ACC2(ac[4],c0,v2); ACC2(ac[5],c1,v2); ACC2(ac[6],c0,v3); ACC2(ac[7],c1,v3);

__global__ void __launch_bounds__(256, 1)
gru_persistent(const float* __restrict__ X,
               const float* __restrict__ Wz, const float* __restrict__ bz,
               const float* __restrict__ Wr, const float* __restrict__ br,
               const float* __restrict__ Wc, const float* __restrict__ bc,
               float* __restrict__ out)
{
    extern __shared__ float sm[];
    float* wT = sm;                       // 18432 floats, k-major interleaved
    float* sB = sm + 18432;               // 48
    const int tid  = threadIdx.x;
    const int half = tid >> 7, lt = tid & 127;
    const int w = lt >> 5, l = lt & 31, rr = l & 3, cc = l >> 2;
    const int bt = blockIdx.x & 7, hsb = blockIdx.x >> 3;
    const int bbase = bt * 32 + half * 16, jbase = hsb * 16;
    const int nb = 1 + half;
    float* hb   = sm + 18480 + half * 12480;
    float* h_s  = hb;                     // 16 x 260
    float* rh_s = hb + 4160;              // 16 x 260
    float* x_s  = hb + 8320;              // 16 x 132
    float* red  = hb + 10432;             // 2048

    unsigned* cnt = &g_count[(bt * 2 + half) * 32];
    unsigned* sns = &g_sense[(bt * 2 + half) * 32];
    unsigned sense = 0;
    if (lt == 0) sense = *((volatile unsigned *)sns);

    {   // weights: k-major, col pairs interleaved (slot = (c>>1) + 8*(c&1))
        float4* wp = (float4*)wT;
        for (int idx = tid; idx < 3 * WT4; idx += 256) {
            int g = idx / WT4, rem = idx % WT4, k4 = rem >> 4, c = rem & 15;
            const float4* W4 = (const float4*)((g == 0) ? Wz : (g == 1) ? Wr : Wc);
            wp[(g * 96 + k4) * 16 + ((c >> 1) + 8 * (c & 1))] = W4[(jbase + c) * 96 + k4];
        }
        if (tid < 16) {
            sB[tid] = bz[jbase + tid]; sB[16 + tid] = br[jbase + tid];
            sB[32 + tid] = bc[jbase + tid];
        }
    }
    for (int i = lt; i < 16 * HPADF; i += 128) h_s[i] = 0.0f;
    #pragma unroll
    for (int j = 0; j < 4; j++) {
        int idx = lt + 128 * j, row = idx >> 5, c4 = idx & 31;
        *(float4*)(x_s + row * XPADF + c4 * 4) =
            ((const float4*)X)[(size_t)(bbase + row) * (SEQLEN * 32) + c4];
    }
    __syncthreads();

    const ulonglong2* hA = (const ulonglong2*)(h_s + rr * HPADF);
    const ulonglong2* hB = (const ulonglong2*)(h_s + (rr + 4) * HPADF);
    const ulonglong2* hC = (const ulonglong2*)(h_s + (rr + 8) * HPADF);
    const ulonglong2* hD = (const ulonglong2*)(h_s + (rr + 12) * HPADF);
    const ulonglong2* rA = (const ulonglong2*)(rh_s + rr * HPADF);
    const ulonglong2* rB = (const ulonglong2*)(rh_s + (rr + 4) * HPADF);
    const ulonglong2* rC = (const ulonglong2*)(rh_s + (rr + 8) * HPADF);
    const ulonglong2* rD = (const ulonglong2*)(rh_s + (rr + 12) * HPADF);
    const ulonglong2* xA = (const ulonglong2*)(x_s + rr * XPADF);
    const ulonglong2* xB = (const ulonglong2*)(x_s + (rr + 4) * XPADF);
    const ulonglong2* xC = (const ulonglong2*)(x_s + (rr + 8) * XPADF);
    const ulonglong2* xD = (const ulonglong2*)(x_s + (rr + 12) * XPADF);
    const ulonglong2* wzp = (const ulonglong2*)wT + cc;
    const ulonglong2* wrp = wzp + WT4;
    const ulonglong2* wcp = wzp + 2 * WT4;
    const int kw = w * 16, kx = w * 8, sw = w ^ rr;
    const int orow0 = lt >> 4, ocol = lt & 15, orow1 = orow0 + 8;
    const float bzv = sB[ocol], brv = sB[16 + ocol], bcv = sB[32 + ocol];

    unsigned long long az[8], ar[8], ac[8];
    #pragma unroll
    for (int i = 0; i < 8; i++) { az[i] = 0; ar[i] = 0; }
    #pragma unroll 4
    for (int kk = 0; kk < 8; kk++) {            // z/r x-part, t=0
        int k4 = 64 + kx + kk, kq = kx + kk;
        ulonglong2 v0 = xA[kq], v1 = xB[kq], v2 = xC[kq], v3 = xD[kq];
        ulonglong2 z0 = wzp[k4*16], z1 = wzp[k4*16+8];
        ulonglong2 r0 = wrp[k4*16], r1 = wrp[k4*16+8];
        ZR16(v0,v1,v2,v3,z0,z1,r0,r1)
    }

    for (int t = 0; t < SEQLEN; t++) {
        #pragma unroll 4
        for (int kk = 0; kk < 16; kk++) {       // phase1 h-part
            int k4 = kw + kk;
            ulonglong2 v0 = hA[k4], v1 = hB[k4], v2 = hC[k4], v3 = hD[k4];
            ulonglong2 z0 = wzp[k4*16], z1 = wzp[k4*16+8];
            ulonglong2 r0 = wrp[k4*16], r1 = wrp[k4*16+8];
            ZR16(v0,v1,v2,v3,z0,z1,r0,r1)
        }
        #pragma unroll
        for (int i = 0; i < 4; i++)
            #pragma unroll
            for (int e = 0; e < 2; e++) {
                int o = (rr + 4*i) * 16 + 2*cc + e;
                red[(o << 2) + sw]         = f2sum(az[i*2+e]);
                red[((256 + o) << 2) + sw] = f2sum(ar[i*2+e]);
            }
        barn(nb);
        float4 p0 = *(float4*)(red + lt*4);
        float4 p1 = *(float4*)(red + (lt+128)*4);
        float4 p2 = *(float4*)(red + (lt+256)*4);
        float4 p3 = *(float4*)(red + (lt+384)*4);
        float zz0 = sig_(p0.x+p0.y+p0.z+p0.w + bzv);
        float zz1 = sig_(p1.x+p1.y+p1.z+p1.w + bzv);
        float rv0 = sig_(p2.x+p2.y+p2.z+p2.w + brv);
        float rv1 = sig_(p3.x+p3.y+p3.z+p3.w + brv);
        float h0o = h_s[orow0 * HPADF + jbase + ocol];
        float h1o = h_s[orow1 * HPADF + jbase + ocol];
        g_rh[(bbase + orow0) * 256 + jbase + ocol] = rv0 * h0o;
        g_rh[(bbase + orow1) * 256 + jbase + ocol] = rv1 * h1o;

        grp_arrive(sense, cnt, sns, nb, lt);        // A arrive
        #pragma unroll
        for (int i = 0; i < 8; i++) ac[i] = 0;
        #pragma unroll 4
        for (int kk = 0; kk < 8; kk++) {            // cand x-part (overlap A)
            int k4 = 64 + kx + kk, kq = kx + kk;
            ulonglong2 v0 = xA[kq], v1 = xB[kq], v2 = xC[kq], v3 = xD[kq];
            ulonglong2 c0 = wcp[k4*16], c1 = wcp[k4*16+8];
            C8(v0,v1,v2,v3,c0,c1)
        }
        grp_wait(sense, sns, nb, lt);               // A wait

        #pragma unroll
        for (int j = 0; j < 8; j++) {               // rh gather
            int idx = lt + 128*j, row = idx >> 6, c4 = idx & 63;
            *(float4*)(rh_s + row * HPADF + c4 * 4) =
                ((const float4*)g_rh)[(bbase + row) * 64 + c4];
        }
        barn(nb);

        #pragma unroll 4
        for (int kk = 0; kk < 16; kk++) {           // phase2 h-part
            int k4 = kw + kk;
            ulonglong2 v0 = rA[k4], v1 = rB[k4], v2 = rC[k4], v3 = rD[k4];
            ulonglong2 c0 = wcp[k4*16], c1 = wcp[k4*16+8];
            C8(v0,v1,v2,v3,c0,c1)
        }
        #pragma unroll
        for (int i = 0; i < 4; i++)
            #pragma unroll
            for (int e = 0; e < 2; e++) {
                int o = (rr + 4*i) * 16 + 2*cc + e;
                red[(o << 2) + sw] = f2sum(ac[i*2+e]);
            }
        barn(nb);
        float4 q0 = *(float4*)(red + lt*4);
        float4 q1 = *(float4*)(red + (lt+128)*4);
        float c0v = tanh_(q0.x+q0.y+q0.z+q0.w + bcv);
        float c1v = tanh_(q1.x+q1.y+q1.z+q1.w + bcv);
        float hn0 = h0o + zz0 * (c0v - h0o);
        float hn1 = h1o + zz1 * (c1v - h1o);
        g_h[(bbase + orow0) * 256 + jbase + ocol] = hn0;
        g_h[(bbase + orow1) * 256 + jbase + ocol] = hn1;
        out[((size_t)t * 256 + bbase + orow0) * 256 + jbase + ocol] = hn0;
        out[((size_t)t * 256 + bbase + orow1) * 256 + jbase + ocol] = hn1;

        grp_arrive(sense, cnt, sns, nb, lt);        // B arrive
        #pragma unroll
        for (int i = 0; i < 8; i++) { az[i] = 0; ar[i] = 0; }
        if (t + 1 < SEQLEN) {                       // overlap B: x(t+1) + z/r x-part
            #pragma unroll
            for (int j = 0; j < 4; j++) {
                int idx = lt + 128*j, row = idx >> 5, c4 = idx & 31;
                *(float4*)(x_s + row * XPADF + c4 * 4) =
                    ((const float4*)X)[(size_t)(bbase + row) * (SEQLEN * 32)
                                       + (size_t)(t + 1) * 32 + c4];
            }
            barn(nb);
            #pragma unroll 4
            for (int kk = 0; kk < 8; kk++) {
                int k4 = 64 + kx + kk, kq = kx + kk;
                ulonglong2 v0 = xA[kq], v1 = xB[kq], v2 = xC[kq], v3 = xD[kq];
                ulonglong2 z0 = wzp[k4*16], z1 = wzp[k4*16+8];
                ulonglong2 r0 = wrp[k4*16], r1 = wrp[k4*16+8];
                ZR16(v0,v1,v2,v3,z0,z1,r0,r1)
            }
        }
        grp_wait(sense, sns, nb, lt);               // B wait
        if (t + 1 < SEQLEN) {
            #pragma unroll
            for (int j = 0; j < 8; j++) {           // h gather
                int idx = lt + 128*j, row = idx >> 6, c4 = idx & 63;
                *(float4*)(h_s + row * HPADF + c4 * 4) =
                    ((const float4*)g_h)[(bbase + row) * 64 + c4];
            }
            barn(nb);
        }
    }
}

extern "C" void kernel_launch(void* const* d_in, const int* in_sizes, int n_in,
                              void* d_out, int out_size) {
    const float* X  = (const float*)d_in[0];
    const float* Wz = (const float*)d_in[1];
    const float* bz = (const float*)d_in[2];
    const float* Wr = (const float*)d_in[3];
    const float* br = (const float*)d_in[4];
    const float* Wc = (const float*)d_in[5];
    const float* bc = (const float*)d_in[6];
    float* out = (float*)d_out;

    int smem_bytes = (18480 + 2 * 12480) * (int)sizeof(float);   // 173,760 B
    cudaFuncSetAttribute(gru_persistent,
                         cudaFuncAttributeMaxDynamicSharedMemorySize, smem_bytes);
    gru_persistent<<<128, 256, smem_bytes>>>(X, Wz, bz, Wr, br, Wc, bc, out);
}

// round 10
// speedup vs baseline: 1.6170x; 1.0710x over previous
#include <cuda_runtime.h>

// GRU persistent v5 = v4 + deterministic anti-phase stagger of the two
// half-pipelines + MLP-staged gathers + out-stores moved into overlap window.
#define SEQLEN 512
#define HPADF  260
#define XPADF  132
#define WT4    1536

__device__ float    g_h [256 * 256];
__device__ float    g_rh[256 * 256];
__device__ unsigned g_count[16 * 32];
__device__ unsigned g_sense[16 * 32];

__device__ __forceinline__ void ffma2(unsigned long long &a,
                                      unsigned long long x, unsigned long long y) {
    asm("fma.rn.f32x2 %0, %1, %2, %0;" : "+l"(a) : "l"(x), "l"(y));
}
__device__ __forceinline__ float f2sum(unsigned long long v) {
    return __uint_as_float((unsigned)v) + __uint_as_float((unsigned)(v >> 32));
}
__device__ __forceinline__ float sig_(float a) { return 1.0f / (1.0f + __expf(-a)); }
__device__ __forceinline__ float tanh_(float a) { return 2.0f / (1.0f + __expf(-2.0f * a)) - 1.0f; }
__device__ __forceinline__ void barn(int id) {
    asm volatile("bar.sync %0, 128;" :: "r"(id) : "memory");
}
__device__ __forceinline__ void grp_arrive(unsigned &sense, unsigned *cnt,
                                           unsigned *sns, int nb, int lt) {
    barn(nb);
    if (lt == 0) {
        sense ^= 1u;
        __threadfence();
        if (atomicAdd(cnt, 1u) == 15u) {
            atomicExch(cnt, 0u);
            __threadfence();
            atomicExch(sns, sense);
        }
    }
}
__device__ __forceinline__ void grp_wait(unsigned sense, unsigned *sns, int nb, int lt) {
    if (lt == 0) {
        while (*((volatile unsigned *)sns) != sense) { }
        __threadfence();
    }
    barn(nb);
}

#define ACC2(a, wv, hv) { ffma2(a, (wv).x, (hv).x); ffma2(a, (wv).y, (hv).y); }
#define ZR16(v0,v1,v2,v3,z0,z1,r0,r1) \
    ACC2(az[0],z0,v0); ACC2(az[1],z1,v0); ACC2(az[2],z0,v1); ACC2(az[3],z1,v1); \
    ACC2(az[4],z0,v2); ACC2(az[5],z1,v2); ACC2(az[6],z0,v3); ACC2(az[7],z1,v3); \
    ACC2(ar[0],r0,v0); ACC2(ar[1],r1,v0); ACC2(ar[2],r0,v1); ACC2(ar[3],r1,v1); \
    ACC2(ar[4],r0,v2); ACC2(ar[5],r1,v2); ACC2(ar[6],r0,v3); ACC2(ar[7],r1,v3);
#define C8(v0,v1,v2,v3,c0,c1) \
    ACC2(ac[0],c0,v0); ACC2(ac[1],c1,v0); ACC2(ac[2],c0,v1); ACC2(ac[3],c1,v1); \
    ACC2(ac[4],c0,v2); ACC2(ac[5],c1,v2); ACC2(ac[6],c0,v3); ACC2(ac[7],c1,v3);

__global__ void __launch_bounds__(256, 1)
gru_persistent(const float* __restrict__ X,
               const float* __restrict__ Wz, const float* __restrict__ bz,
               const float* __restrict__ Wr, const float* __restrict__ br,
               const float* __restrict__ Wc, const float* __restrict__ bc,
               float* __restrict__ out)
{
    extern __shared__ float sm[];
    float* wT = sm;                       // 18432 floats, k-major interleaved
    float* sB = sm + 18432;               // 48
    const int tid  = threadIdx.x;
    const int half = tid >> 7, lt = tid & 127;
    const int w = lt >> 5, l = lt & 31, rr = l & 3, cc = l >> 2;
    const int bt = blockIdx.x & 7, hsb = blockIdx.x >> 3;
    const int bbase = bt * 32 + half * 16, jbase = hsb * 16;
    const int nb = 1 + half;
    float* hb   = sm + 18480 + half * 12480;
    float* h_s  = hb;                     // 16 x 260
    float* rh_s = hb + 4160;              // 16 x 260
    float* x_s  = hb + 8320;              // 16 x 132
    float* red  = hb + 10432;             // 2048

    unsigned* cnt = &g_count[(bt * 2 + half) * 32];
    unsigned* sns = &g_sense[(bt * 2 + half) * 32];
    unsigned sense = 0;
    if (lt == 0) sense = *((volatile unsigned *)sns);

    {   // weights: k-major, col pairs interleaved (slot = (c>>1) + 8*(c&1))
        float4* wp = (float4*)wT;
        for (int idx = tid; idx < 3 * WT4; idx += 256) {
            int g = idx / WT4, rem = idx % WT4, k4 = rem >> 4, c = rem & 15;
            const float4* W4 = (const float4*)((g == 0) ? Wz : (g == 1) ? Wr : Wc);
            wp[(g * 96 + k4) * 16 + ((c >> 1) + 8 * (c & 1))] = W4[(jbase + c) * 96 + k4];
        }
        if (tid < 16) {
            sB[tid] = bz[jbase + tid]; sB[16 + tid] = br[jbase + tid];
            sB[32 + tid] = bc[jbase + tid];
        }
    }
    for (int i = lt; i < 16 * HPADF; i += 128) h_s[i] = 0.0f;
    #pragma unroll
    for (int j = 0; j < 4; j++) {
        int idx = lt + 128 * j, row = idx >> 5, c4 = idx & 31;
        *(float4*)(x_s + row * XPADF + c4 * 4) =
            ((const float4*)X)[(size_t)(bbase + row) * (SEQLEN * 32) + c4];
    }
    __syncthreads();

    const ulonglong2* hA = (const ulonglong2*)(h_s + rr * HPADF);
    const ulonglong2* hB = (const ulonglong2*)(h_s + (rr + 4) * HPADF);
    const ulonglong2* hC = (const ulonglong2*)(h_s + (rr + 8) * HPADF);
    const ulonglong2* hD = (const ulonglong2*)(h_s + (rr + 12) * HPADF);
    const ulonglong2* rA = (const ulonglong2*)(rh_s + rr * HPADF);
    const ulonglong2* rB = (const ulonglong2*)(rh_s + (rr + 4) * HPADF);
    const ulonglong2* rC = (const ulonglong2*)(rh_s + (rr + 8) * HPADF);
    const ulonglong2* rD = (const ulonglong2*)(rh_s + (rr + 12) * HPADF);
    const ulonglong2* xA = (const ulonglong2*)(x_s + rr * XPADF);
    const ulonglong2* xB = (const ulonglong2*)(x_s + (rr + 4) * XPADF);
    const ulonglong2* xC = (const ulonglong2*)(x_s + (rr + 8) * XPADF);
    const ulonglong2* xD = (const ulonglong2*)(x_s + (rr + 12) * XPADF);
    const ulonglong2* wzp = (const ulonglong2*)wT + cc;
    const ulonglong2* wrp = wzp + WT4;
    const ulonglong2* wcp = wzp + 2 * WT4;
    const int kw = w * 16, kx = w * 8, sw = w ^ rr;
    const int orow0 = lt >> 4, ocol = lt & 15, orow1 = orow0 + 8;
    const float bzv = sB[ocol], brv = sB[16 + ocol], bcv = sB[32 + ocol];

    unsigned long long az[8], ar[8], ac[8];
    #pragma unroll
    for (int i = 0; i < 8; i++) { az[i] = 0; ar[i] = 0; }
    #pragma unroll 4
    for (int kk = 0; kk < 8; kk++) {            // z/r x-part, t=0
        int k4 = 64 + kx + kk, kq = kx + kk;
        ulonglong2 v0 = xA[kq], v1 = xB[kq], v2 = xC[kq], v3 = xD[kq];
        ulonglong2 z0 = wzp[k4*16], z1 = wzp[k4*16+8];
        ulonglong2 r0 = wrp[k4*16], r1 = wrp[k4*16+8];
        ZR16(v0,v1,v2,v3,z0,z1,r0,r1)
    }

    // ---- anti-phase stagger: half 1 runs the phase1 h-loop twice extra.
    // h_s is all zeros here, so these passes add exactly 0 to az/ar (numeric
    // identity), but delay half 1 by ~half a step period. Both halves keep
    // identical per-step periods afterward, so the offset persists and each
    // half's compute covers the other half's barrier/gather stalls.
    if (half == 1) {
        #pragma unroll 1
        for (int d = 0; d < 2; d++) {
            #pragma unroll 4
            for (int kk = 0; kk < 16; kk++) {
                int k4 = kw + kk;
                ulonglong2 v0 = hA[k4], v1 = hB[k4], v2 = hC[k4], v3 = hD[k4];
                ulonglong2 z0 = wzp[k4*16], z1 = wzp[k4*16+8];
                ulonglong2 r0 = wrp[k4*16], r1 = wrp[k4*16+8];
                ZR16(v0,v1,v2,v3,z0,z1,r0,r1)
            }
        }
    }

    for (int t = 0; t < SEQLEN; t++) {
        #pragma unroll 4
        for (int kk = 0; kk < 16; kk++) {       // phase1 h-part
            int k4 = kw + kk;
            ulonglong2 v0 = hA[k4], v1 = hB[k4], v2 = hC[k4], v3 = hD[k4];
            ulonglong2 z0 = wzp[k4*16], z1 = wzp[k4*16+8];
            ulonglong2 r0 = wrp[k4*16], r1 = wrp[k4*16+8];
            ZR16(v0,v1,v2,v3,z0,z1,r0,r1)
        }
        #pragma unroll
        for (int i = 0; i < 4; i++)
            #pragma unroll
            for (int e = 0; e < 2; e++) {
                int o = (rr + 4*i) * 16 + 2*cc + e;
                red[(o << 2) + sw]         = f2sum(az[i*2+e]);
                red[((256 + o) << 2) + sw] = f2sum(ar[i*2+e]);
            }
        barn(nb);
        float4 p0 = *(float4*)(red + lt*4);
        float4 p1 = *(float4*)(red + (lt+128)*4);
        float4 p2 = *(float4*)(red + (lt+256)*4);
        float4 p3 = *(float4*)(red + (lt+384)*4);
        float zz0 = sig_(p0.x+p0.y+p0.z+p0.w + bzv);
        float zz1 = sig_(p1.x+p1.y+p1.z+p1.w + bzv);
        float rv0 = sig_(p2.x+p2.y+p2.z+p2.w + brv);
        float rv1 = sig_(p3.x+p3.y+p3.z+p3.w + brv);
        float h0o = h_s[orow0 * HPADF + jbase + ocol];
        float h1o = h_s[orow1 * HPADF + jbase + ocol];
        g_rh[(bbase + orow0) * 256 + jbase + ocol] = rv0 * h0o;
        g_rh[(bbase + orow1) * 256 + jbase + ocol] = rv1 * h1o;

        grp_arrive(sense, cnt, sns, nb, lt);        // A arrive
        #pragma unroll
        for (int i = 0; i < 8; i++) ac[i] = 0;
        #pragma unroll 4
        for (int kk = 0; kk < 8; kk++) {            // cand x-part (overlap A)
            int k4 = 64 + kx + kk, kq = kx + kk;
            ulonglong2 v0 = xA[kq], v1 = xB[kq], v2 = xC[kq], v3 = xD[kq];
            ulonglong2 c0 = wcp[k4*16], c1 = wcp[k4*16+8];
            C8(v0,v1,v2,v3,c0,c1)
        }
        grp_wait(sense, sns, nb, lt);               // A wait

        {   // rh gather: stage all 8 LDGs first (MLP=8), then 8 STS
            float4 tmp[8];
            #pragma unroll
            for (int j = 0; j < 8; j++) {
                int idx = lt + 128*j;
                tmp[j] = ((const float4*)g_rh)[(bbase + (idx >> 6)) * 64 + (idx & 63)];
            }
            #pragma unroll
            for (int j = 0; j < 8; j++) {
                int idx = lt + 128*j;
                *(float4*)(rh_s + (idx >> 6) * HPADF + (idx & 63) * 4) = tmp[j];
            }
        }
        barn(nb);

        #pragma unroll 4
        for (int kk = 0; kk < 16; kk++) {           // phase2 h-part
            int k4 = kw + kk;
            ulonglong2 v0 = rA[k4], v1 = rB[k4], v2 = rC[k4], v3 = rD[k4];
            ulonglong2 c0 = wcp[k4*16], c1 = wcp[k4*16+8];
            C8(v0,v1,v2,v3,c0,c1)
        }
        #pragma unroll
        for (int i = 0; i < 4; i++)
            #pragma unroll
            for (int e = 0; e < 2; e++) {
                int o = (rr + 4*i) * 16 + 2*cc + e;
                red[(o << 2) + sw] = f2sum(ac[i*2+e]);
            }
        barn(nb);
        float4 q0 = *(float4*)(red + lt*4);
        float4 q1 = *(float4*)(red + (lt+128)*4);
        float c0v = tanh_(q0.x+q0.y+q0.z+q0.w + bcv);
        float c1v = tanh_(q1.x+q1.y+q1.z+q1.w + bcv);
        float hn0 = h0o + zz0 * (c0v - h0o);
        float hn1 = h1o + zz1 * (c1v - h1o);
        g_h[(bbase + orow0) * 256 + jbase + ocol] = hn0;
        g_h[(bbase + orow1) * 256 + jbase + ocol] = hn1;

        grp_arrive(sense, cnt, sns, nb, lt);        // B arrive

        // overlap B: out stores (fire-and-forget) + x(t+1) + z/r x-part
        out[((size_t)t * 256 + bbase + orow0) * 256 + jbase + ocol] = hn0;
        out[((size_t)t * 256 + bbase + orow1) * 256 + jbase + ocol] = hn1;
        #pragma unroll
        for (int i = 0; i < 8; i++) { az[i] = 0; ar[i] = 0; }
        if (t + 1 < SEQLEN) {
            float4 xt[4];
            #pragma unroll
            for (int j = 0; j < 4; j++) {
                int idx = lt + 128*j;
                xt[j] = ((const float4*)X)[(size_t)(bbase + (idx >> 5)) * (SEQLEN * 32)
                                           + (size_t)(t + 1) * 32 + (idx & 31)];
            }
            #pragma unroll
            for (int j = 0; j < 4; j++) {
                int idx = lt + 128*j;
                *(float4*)(x_s + (idx >> 5) * XPADF + (idx & 31) * 4) = xt[j];
            }
            barn(nb);
            #pragma unroll 4
            for (int kk = 0; kk < 8; kk++) {
                int k4 = 64 + kx + kk, kq = kx + kk;
                ulonglong2 v0 = xA[kq], v1 = xB[kq], v2 = xC[kq], v3 = xD[kq];
                ulonglong2 z0 = wzp[k4*16], z1 = wzp[k4*16+8];
                ulonglong2 r0 = wrp[k4*16], r1 = wrp[k4*16+8];
                ZR16(v0,v1,v2,v3,z0,z1,r0,r1)
            }
        }
        grp_wait(sense, sns, nb, lt);               // B wait
        if (t + 1 < SEQLEN) {
            float4 tmp[8];
            #pragma unroll
            for (int j = 0; j < 8; j++) {           // h gather (staged)
                int idx = lt + 128*j;
                tmp[j] = ((const float4*)g_h)[(bbase + (idx >> 6)) * 64 + (idx & 63)];
            }
            #pragma unroll
            for (int j = 0; j < 8; j++) {
                int idx = lt + 128*j;
                *(float4*)(h_s + (idx >> 6) * HPADF + (idx & 63) * 4) = tmp[j];
            }
            barn(nb);
        }
    }
}

extern "C" void kernel_launch(void* const* d_in, const int* in_sizes, int n_in,
                              void* d_out, int out_size) {
    const float* X  = (const float*)d_in[0];
    const float* Wz = (const float*)d_in[1];
    const float* bz = (const float*)d_in[2];
    const float* Wr = (const float*)d_in[3];
    const float* br = (const float*)d_in[4];
    const float* Wc = (const float*)d_in[5];
    const float* bc = (const float*)d_in[6];
    float* out = (float*)d_out;

    int smem_bytes = (18480 + 2 * 12480) * (int)sizeof(float);   // 173,760 B
    cudaFuncSetAttribute(gru_persistent,
                         cudaFuncAttributeMaxDynamicSharedMemorySize, smem_bytes);
    gru_persistent<<<128, 256, smem_bytes>>>(X, Wz, bz, Wr, br, Wc, bc, out);
}